// round 1
// baseline (speedup 1.0000x reference)
#include <cuda_runtime.h>

#define NB      2
#define CC      512
#define SS      256
#define CTILE   8
#define DCHUNK  32
#define NCHUNK  (CC / DCHUNK)   // 16
#define THREADS 256

// smem layout (dynamic):
//  ks: [2][DCHUNK][SS]  = 65536 B
//  vs: [2][DCHUNK][SS]  = 65536 B
//  red:[8][32][33]      = 33792 B
#define SMEM_BYTES (2*DCHUNK*SS*4 * 2 + 8*32*33*4)

__device__ __forceinline__ void cp_async16(void* sdst, const void* gsrc) {
    unsigned a = (unsigned)__cvta_generic_to_shared(sdst);
    asm volatile("cp.async.cg.shared.global [%0], [%1], 16;\n" :: "r"(a), "l"(gsrc));
}

extern __shared__ __align__(16) float smem[];

__global__ void __launch_bounds__(THREADS, 1)
laplace_attn_kernel(const float* __restrict__ q,
                    const float* __restrict__ k,
                    const float* __restrict__ v,
                    float* __restrict__ out)
{
    float* ks  = smem;                      // [2][DCHUNK][SS]
    float* vs  = smem + 2*DCHUNK*SS;        // [2][DCHUNK][SS]
    float* red = smem + 4*DCHUNK*SS;        // [8][32][33]

    const int tid = threadIdx.x;
    const int w   = tid >> 5;               // warp = c within tile
    const int l   = tid & 31;               // lane = s-slice owner
    const int n   = blockIdx.x / (CC / CTILE);
    const int ct  = blockIdx.x % (CC / CTILE);
    const int c   = ct * CTILE + w;

    // q row slice in registers (loaded once for whole kernel)
    const float* qrow = q + ((size_t)n*CC + c)*SS + l*8;
    const float4 q0 = *(const float4*)qrow;
    const float4 q1 = *(const float4*)(qrow + 4);

    const float* kbase = k + (size_t)n*CC*SS;
    const float* vbase = v + (size_t)n*CC*SS;

    float acc[8];
#pragma unroll
    for (int j = 0; j < 8; j++) acc[j] = 0.f;
    float m    = -1e30f;
    float lsum = 0.f;

    // prologue: stage chunk 0 into buffer 0
    {
        const float4* kg = (const float4*)kbase;
        const float4* vg = (const float4*)vbase;
#pragma unroll
        for (int j = 0; j < 8; j++) {
            int idx = tid + j*THREADS;      // 2048 float4 per tensor chunk
            cp_async16(ks + idx*4, kg + idx);
            cp_async16(vs + idx*4, vg + idx);
        }
        asm volatile("cp.async.commit_group;\n" ::: "memory");
    }

    for (int ch = 0; ch < NCHUNK; ch++) {
        const int p = ch & 1;

        // issue next chunk into the other buffer (safe: trailing
        // __syncthreads of iteration ch-1 guarantees buffer 1-p is idle)
        if (ch + 1 < NCHUNK) {
            const float4* kg = (const float4*)(kbase + (size_t)(ch+1)*DCHUNK*SS);
            const float4* vg = (const float4*)(vbase + (size_t)(ch+1)*DCHUNK*SS);
            float* kd = ks + (1 - p)*DCHUNK*SS;
            float* vd = vs + (1 - p)*DCHUNK*SS;
#pragma unroll
            for (int j = 0; j < 8; j++) {
                int idx = tid + j*THREADS;
                cp_async16(kd + idx*4, kg + idx);
                cp_async16(vd + idx*4, vg + idx);
            }
            asm volatile("cp.async.commit_group;\n" ::: "memory");
            asm volatile("cp.async.wait_group 1;\n" ::: "memory");
        } else {
            asm volatile("cp.async.wait_group 0;\n" ::: "memory");
        }
        __syncthreads();

        const float* kc = ks + p*DCHUNK*SS;
        const float* vc = vs + p*DCHUNK*SS;
        float* rw = red + w*32*33;

        // ---- distance partials: lane sums its 8 s-values for each d ----
#pragma unroll
        for (int d = 0; d < DCHUNK; d++) {
            const float* kr = kc + d*SS + l*8;
            const float4 a = *(const float4*)kr;
            const float4 b = *(const float4*)(kr + 4);
            float t0 = fabsf(a.x - q0.x) + fabsf(a.y - q0.y);
            float t1 = fabsf(a.z - q0.z) + fabsf(a.w - q0.w);
            float t2 = fabsf(b.x - q1.x) + fabsf(b.y - q1.y);
            float t3 = fabsf(b.z - q1.z) + fabsf(b.w - q1.w);
            rw[d*33 + l] = (t0 + t1) + (t2 + t3);
        }
        __syncwarp();

        // ---- transpose-reduce: lane l gathers full dist for d = l ----
        float s0 = 0.f, s1 = 0.f, s2 = 0.f, s3 = 0.f;
#pragma unroll
        for (int i = 0; i < 32; i += 4) {
            s0 += rw[l*33 + i + 0];
            s1 += rw[l*33 + i + 1];
            s2 += rw[l*33 + i + 2];
            s3 += rw[l*33 + i + 3];
        }
        const float dist = (s0 + s1) + (s2 + s3);
        const float wv   = -0.5f * dist;      // logits = -dist/SCALE, SCALE=2

        // ---- online softmax (per warp = per c-row) ----
        float cm = wv;
#pragma unroll
        for (int off = 16; off; off >>= 1)
            cm = fmaxf(cm, __shfl_xor_sync(0xffffffffu, cm, off));
        const float mnew = fmaxf(m, cm);
        const float corr = __expf(m - mnew);
        const float pv   = __expf(wv - mnew);
        float csum = pv;
#pragma unroll
        for (int off = 16; off; off >>= 1)
            csum += __shfl_xor_sync(0xffffffffu, csum, off);
        lsum = lsum*corr + csum;
        m = mnew;
#pragma unroll
        for (int j = 0; j < 8; j++) acc[j] *= corr;

        // ---- P @ V accumulate: p broadcast via shfl, v via LDS.128 ----
#pragma unroll
        for (int d = 0; d < DCHUNK; d++) {
            const float pj = __shfl_sync(0xffffffffu, pv, d);
            const float* vr = vc + d*SS + l*8;
            const float4 a = *(const float4*)vr;
            const float4 b = *(const float4*)(vr + 4);
            acc[0] += pj*a.x; acc[1] += pj*a.y;
            acc[2] += pj*a.z; acc[3] += pj*a.w;
            acc[4] += pj*b.x; acc[5] += pj*b.y;
            acc[6] += pj*b.z; acc[7] += pj*b.w;
        }
        __syncthreads();   // buffer p reusable; also protects red region
    }

    const float inv = 1.f / lsum;
    float* orow = out + ((size_t)n*CC + c)*SS + l*8;
    float4 o0, o1;
    o0.x = acc[0]*inv; o0.y = acc[1]*inv; o0.z = acc[2]*inv; o0.w = acc[3]*inv;
    o1.x = acc[4]*inv; o1.y = acc[5]*inv; o1.z = acc[6]*inv; o1.w = acc[7]*inv;
    *(float4*)orow       = o0;
    *(float4*)(orow + 4) = o1;
}

extern "C" void kernel_launch(void* const* d_in, const int* in_sizes, int n_in,
                              void* d_out, int out_size) {
    const float* q = (const float*)d_in[0];
    const float* k = (const float*)d_in[1];
    const float* v = (const float*)d_in[2];
    float* out = (float*)d_out;

    cudaFuncSetAttribute(laplace_attn_kernel,
                         cudaFuncAttributeMaxDynamicSharedMemorySize, SMEM_BYTES);

    laplace_attn_kernel<<<NB * (CC / CTILE), THREADS, SMEM_BYTES>>>(q, k, v, out);
}

// round 2
// speedup vs baseline: 2.0901x; 2.0901x over previous
#include <cuda_runtime.h>

#define NB      2
#define CC      512
#define SS      256
#define DCHUNK  32
#define NCHUNK  (CC / DCHUNK)     // 16
#define THREADS 512
#define WARPS   16

// smem (floats): ks/vs double-buffered: 4*DCHUNK*SS = 32768 floats (131072 B)
// rw (per-warp reduce scratch): WARPS * 16 * 33 = 8448 floats (33792 B)
#define KS_FLOATS   (2 * DCHUNK * SS)
#define SMEM_FLOATS (4 * DCHUNK * SS + WARPS * 16 * 33)
#define SMEM_BYTES  (SMEM_FLOATS * 4)

typedef unsigned long long ull;

__device__ __forceinline__ ull add2(ull a, ull b) {
    ull c; asm("add.rn.f32x2 %0, %1, %2;" : "=l"(c) : "l"(a), "l"(b)); return c;
}
__device__ __forceinline__ ull mul2(ull a, ull b) {
    ull c; asm("mul.rn.f32x2 %0, %1, %2;" : "=l"(c) : "l"(a), "l"(b)); return c;
}
__device__ __forceinline__ ull fma2(ull a, ull b, ull c) {
    ull d; asm("fma.rn.f32x2 %0, %1, %2, %3;" : "=l"(d) : "l"(a), "l"(b), "l"(c)); return d;
}
__device__ __forceinline__ ull abs2(ull a) {
    return a & 0x7FFFFFFF7FFFFFFFULL;           // 2x LOP3 on the idle ALU pipe
}
__device__ __forceinline__ ull pack2(float x, float y) {
    ull r; asm("mov.b64 %0, {%1, %2};" : "=l"(r) : "f"(x), "f"(y)); return r;
}
__device__ __forceinline__ ull dup2(float x) { return pack2(x, x); }
__device__ __forceinline__ float hadd2(ull a) {
    float lo = __uint_as_float((unsigned)a);
    float hi = __uint_as_float((unsigned)(a >> 32));
    return lo + hi;
}
__device__ __forceinline__ void cp_async16(void* sdst, const void* gsrc) {
    unsigned a = (unsigned)__cvta_generic_to_shared(sdst);
    asm volatile("cp.async.cg.shared.global [%0], [%1], 16;\n" :: "r"(a), "l"(gsrc));
}

extern __shared__ __align__(16) float smem[];

__device__ __forceinline__ void stage_chunk(const float* kg, const float* vg,
                                            float* kd, float* vd, int tid) {
    const float4* kg4 = (const float4*)kg;
    const float4* vg4 = (const float4*)vg;
#pragma unroll
    for (int j = 0; j < 4; j++) {               // 2048 float4 per tensor / 512 thr
        int idx = tid + j * THREADS;
        cp_async16(kd + idx * 4, kg4 + idx);
        cp_async16(vd + idx * 4, vg4 + idx);
    }
    asm volatile("cp.async.commit_group;\n" ::: "memory");
}

__global__ void __launch_bounds__(THREADS, 1)
laplace_attn_kernel(const float* __restrict__ q,
                    const float* __restrict__ k,
                    const float* __restrict__ v,
                    float* __restrict__ out)
{
    float* ks = smem;                            // [2][DCHUNK][SS]
    float* vs = smem + KS_FLOATS;                // [2][DCHUNK][SS]
    float* rwb = smem + 4 * DCHUNK * SS;         // [WARPS][16][33]

    const int tid = threadIdx.x;
    const int w   = tid >> 5;
    const int l   = tid & 31;
    const int g   = w & 1;                       // row-group (4 rows each)
    const int ds  = w >> 1;                      // d-split 0..7 (4 d's of each 32-chunk)
    const int n   = blockIdx.x / (CC / 8);
    const int ct  = blockIdx.x % (CC / 8);
    const int c0  = ct * 8 + g * 4;              // first of this warp's 4 rows

    float* rw = rwb + w * (16 * 33);

    // q rows, negated + packed (so distance = add2(k, nq))
    ull nq[4][4];
#pragma unroll
    for (int r = 0; r < 4; r++) {
        const float* qp = q + ((size_t)n * CC + c0 + r) * SS + l * 8;
        float4 a = *(const float4*)qp;
        float4 b = *(const float4*)(qp + 4);
        nq[r][0] = pack2(-a.x, -a.y);
        nq[r][1] = pack2(-a.z, -a.w);
        nq[r][2] = pack2(-b.x, -b.y);
        nq[r][3] = pack2(-b.z, -b.w);
    }

    const float* kbase = k + (size_t)n * CC * SS;
    const float* vbase = v + (size_t)n * CC * SS;

    ull acc[4][4];
#pragma unroll
    for (int r = 0; r < 4; r++)
#pragma unroll
        for (int j = 0; j < 4; j++) acc[r][j] = 0ULL;

    float m_own = -1e30f;                        // per-lane row = (l&15)>>2, fixed
    float lsum_own = 0.f;

    stage_chunk(kbase, vbase, ks, vs, tid);      // chunk 0 -> buffer 0

#pragma unroll 1
    for (int ch = 0; ch < NCHUNK; ch++) {
        const int p = ch & 1;
        if (ch + 1 < NCHUNK) {
            stage_chunk(kbase + (size_t)(ch + 1) * DCHUNK * SS,
                        vbase + (size_t)(ch + 1) * DCHUNK * SS,
                        ks + (1 - p) * DCHUNK * SS,
                        vs + (1 - p) * DCHUNK * SS, tid);
            asm volatile("cp.async.wait_group 1;\n" ::: "memory");
        } else {
            asm volatile("cp.async.wait_group 0;\n" ::: "memory");
        }
        __syncthreads();

        const float* kc = ks + p * DCHUNK * SS;
        const float* vc = vs + p * DCHUNK * SS;

        // ---- distance partials: 4 d's x 4 rows, packed f32x2 ----
#pragma unroll
        for (int dl = 0; dl < 4; dl++) {
            const int d = ds * 4 + dl;
            const ulonglong2* kp = (const ulonglong2*)(kc + d * SS + l * 8);
            ulonglong2 ka = kp[0], kb = kp[1];
#pragma unroll
            for (int r = 0; r < 4; r++) {
                ull t0 = abs2(add2(ka.x, nq[r][0]));
                ull t1 = abs2(add2(ka.y, nq[r][1]));
                ull t2 = abs2(add2(kb.x, nq[r][2]));
                ull t3 = abs2(add2(kb.y, nq[r][3]));
                ull s  = add2(add2(t0, t1), add2(t2, t3));
                rw[(r * 4 + dl) * 33 + l] = hadd2(s);
            }
        }
        __syncwarp();

        // ---- transpose-reduce: lane pair per (row,d) entry ----
        const int e = l & 15;                    // e = row*4 + dl
        const int h = l >> 4;
        const float* rr = rw + e * 33 + h * 16;
        float s0 = 0.f, s1 = 0.f, s2 = 0.f, s3 = 0.f;
#pragma unroll
        for (int j = 0; j < 16; j += 4) {
            s0 += rr[j + 0]; s1 += rr[j + 1];
            s2 += rr[j + 2]; s3 += rr[j + 3];
        }
        float dist = (s0 + s1) + (s2 + s3);
        dist += __shfl_xor_sync(0xffffffffu, dist, 16);
        const float wv = -0.5f * dist;           // logits = -dist/SCALE, SCALE=2

        // ---- per-warp online softmax over this warp's 4-d segment ----
        float cm = wv;
        cm = fmaxf(cm, __shfl_xor_sync(0xffffffffu, cm, 1));
        cm = fmaxf(cm, __shfl_xor_sync(0xffffffffu, cm, 2));
        const float mnew = fmaxf(m_own, cm);
        const float corr = __expf(m_own - mnew);
        const float pv   = __expf(wv - mnew);
        float ps = pv + __shfl_xor_sync(0xffffffffu, pv, 1);
        ps += __shfl_xor_sync(0xffffffffu, ps, 2);
        lsum_own = lsum_own * corr + ps;
        m_own = mnew;
#pragma unroll
        for (int r = 0; r < 4; r++) {
            const float cr = __shfl_sync(0xffffffffu, corr, r * 4);
            const ull c2 = dup2(cr);
#pragma unroll
            for (int j = 0; j < 4; j++) acc[r][j] = mul2(acc[r][j], c2);
        }

        // ---- P @ V: packed FMA, p broadcast via shfl ----
#pragma unroll
        for (int dl = 0; dl < 4; dl++) {
            const int d = ds * 4 + dl;
            const ulonglong2* vp = (const ulonglong2*)(vc + d * SS + l * 8);
            ulonglong2 va = vp[0], vb = vp[1];
#pragma unroll
            for (int r = 0; r < 4; r++) {
                const float pj = __shfl_sync(0xffffffffu, pv, r * 4 + dl);
                const ull p2 = dup2(pj);
                acc[r][0] = fma2(p2, va.x, acc[r][0]);
                acc[r][1] = fma2(p2, va.y, acc[r][1]);
                acc[r][2] = fma2(p2, vb.x, acc[r][2]);
                acc[r][3] = fma2(p2, vb.y, acc[r][3]);
            }
        }
        __syncthreads();                         // buffer p reusable
    }

    // ================= epilogue: merge the 8 d-split segments =================
    float* accbuf = smem;                        // [8 rows][8 splits][256] (reuses ks)
    float* stats  = smem + 8 * 8 * 256;          // [8 rows][8 splits][2]  (reuses vs)

#pragma unroll
    for (int r = 0; r < 4; r++) {
        const int row = g * 4 + r;
        float* dst = accbuf + (row * 8 + ds) * 256 + l * 8;
        ((ulonglong2*)dst)[0] = make_ulonglong2(acc[r][0], acc[r][1]);
        ((ulonglong2*)dst)[1] = make_ulonglong2(acc[r][2], acc[r][3]);
    }
    if (l < 16 && (l & 3) == 0) {
        const int row = g * 4 + (l >> 2);
        stats[(row * 8 + ds) * 2 + 0] = m_own;
        stats[(row * 8 + ds) * 2 + 1] = lsum_own;
    }
    __syncthreads();

    {
        const int row  = w >> 1;
        const int half = w & 1;
        const int sb   = half * 128 + l * 4;

        float M = -1e30f;
#pragma unroll
        for (int i = 0; i < 8; i++) M = fmaxf(M, stats[(row * 8 + i) * 2]);

        float L = 0.f;
        ull o0 = 0ULL, o1 = 0ULL;
#pragma unroll
        for (int i = 0; i < 8; i++) {
            const float sc = __expf(stats[(row * 8 + i) * 2] - M);
            L += stats[(row * 8 + i) * 2 + 1] * sc;
            const ulonglong2 a = *(const ulonglong2*)(accbuf + (row * 8 + i) * 256 + sb);
            const ull s2 = dup2(sc);
            o0 = fma2(s2, a.x, o0);
            o1 = fma2(s2, a.y, o1);
        }
        const ull i2 = dup2(1.f / L);
        o0 = mul2(o0, i2);
        o1 = mul2(o1, i2);

        const int c = ct * 8 + row;
        *(ulonglong2*)(out + ((size_t)n * CC + c) * SS + sb) = make_ulonglong2(o0, o1);
    }
}

extern "C" void kernel_launch(void* const* d_in, const int* in_sizes, int n_in,
                              void* d_out, int out_size) {
    const float* q = (const float*)d_in[0];
    const float* k = (const float*)d_in[1];
    const float* v = (const float*)d_in[2];
    float* out = (float*)d_out;

    cudaFuncSetAttribute(laplace_attn_kernel,
                         cudaFuncAttributeMaxDynamicSharedMemorySize, SMEM_BYTES);

    laplace_attn_kernel<<<NB * (CC / 8), THREADS, SMEM_BYTES>>>(q, k, v, out);
}